// round 11
// baseline (speedup 1.0000x reference)
#include <cuda_runtime.h>

#define T_LEN  1024
#define D_DIM  256
#define K_CH   4
#define NCHUNK 128
#define L_CH   8          // T_LEN / NCHUNK
#define NROUND 7          // log2(NCHUNK)
#define DG     4          // d-columns per scan block
#define ATHR   (NCHUNK * DG)   // 512 threads in kernel A

// ================= compile-time HiPPO-LegT constants (double precision) ==========

struct CB {
    float Ab[16];              // Abar row-major
    float Bb[4];               // Bbar
    float Wc[L_CH][4];         // Abar^m * Bbar
    float Pk[NROUND][16];      // Abar^(L_CH * 2^r)
};

constexpr double cfabs(double x) { return x < 0 ? -x : x; }
constexpr double csqrt(double x) {
    double g = x > 1.0 ? x : 1.0;
    for (int i = 0; i < 128; i++) g = 0.5 * (g + x / g);
    return g;
}

struct M4d { double m[4][4]; };

constexpr M4d mm4(const M4d& A, const M4d& B) {
    M4d C{};
    for (int i = 0; i < 4; i++)
        for (int j = 0; j < 4; j++) {
            double s = 0.0;
            for (int k = 0; k < 4; k++) s += A.m[i][k] * B.m[k][j];
            C.m[i][j] = s;
        }
    return C;
}

constexpr M4d inv4(const M4d& Min) {
    double a[4][8] = {};
    for (int i = 0; i < 4; i++)
        for (int j = 0; j < 8; j++)
            a[i][j] = (j < 4) ? Min.m[i][j] : (j - 4 == i ? 1.0 : 0.0);
    for (int col = 0; col < 4; col++) {
        int p = col;
        for (int r = col + 1; r < 4; r++)
            if (cfabs(a[r][col]) > cfabs(a[p][col])) p = r;
        if (p != col)
            for (int j = 0; j < 8; j++) { double t = a[col][j]; a[col][j] = a[p][j]; a[p][j] = t; }
        double piv = a[col][col];
        for (int j = 0; j < 8; j++) a[col][j] /= piv;
        for (int r = 0; r < 4; r++) {
            if (r == col) continue;
            double f = a[r][col];
            for (int j = 0; j < 8; j++) a[r][j] -= f * a[col][j];
        }
    }
    M4d out{};
    for (int i = 0; i < 4; i++)
        for (int j = 0; j < 4; j++) out.m[i][j] = a[i][j + 4];
    return out;
}

constexpr CB build_consts() {
    const double dt = 1.0 / 200.0;      // 1/theta
    double P[4] = {};
    for (int i = 0; i < 4; i++) P[i] = csqrt(2.0 * i + 1.0);
    M4d A{};
    double Bv[4] = {};
    for (int i = 0; i < 4; i++) {
        Bv[i] = P[i];
        for (int j = 0; j < 4; j++) {
            double sg = 1.0;
            if (j > i && ((j - i) & 1)) sg = -1.0;
            A.m[i][j] = -P[i] * P[j] * sg;
        }
    }
    M4d ImA{}, IpA{};
    for (int i = 0; i < 4; i++)
        for (int j = 0; j < 4; j++) {
            double eye = (i == j) ? 1.0 : 0.0;
            ImA.m[i][j] = eye - 0.5 * dt * A.m[i][j];
            IpA.m[i][j] = eye + 0.5 * dt * A.m[i][j];
        }
    M4d Inv = inv4(ImA);
    M4d Abar = mm4(Inv, IpA);
    double Bbar[4] = {};
    for (int i = 0; i < 4; i++) {
        double s = 0.0;
        for (int j = 0; j < 4; j++) s += Inv.m[i][j] * Bv[j] * dt;
        Bbar[i] = s;
    }

    CB r{};
    for (int i = 0; i < 4; i++) {
        r.Bb[i] = (float)Bbar[i];
        for (int j = 0; j < 4; j++) r.Ab[i * 4 + j] = (float)Abar.m[i][j];
    }
    // Wc[m] = Abar^m * Bbar
    double wc[4] = {Bbar[0], Bbar[1], Bbar[2], Bbar[3]};
    for (int m = 0; m < L_CH; m++) {
        for (int i = 0; i < 4; i++) r.Wc[m][i] = (float)wc[i];
        double nw[4] = {};
        for (int i = 0; i < 4; i++) {
            double s = 0.0;
            for (int j = 0; j < 4; j++) s += Abar.m[i][j] * wc[j];
            nw[i] = s;
        }
        for (int i = 0; i < 4; i++) wc[i] = nw[i];
    }
    // Pk[0] = Abar^8, Pk[r] = Pk[r-1]^2
    M4d Q{};
    for (int i = 0; i < 4; i++) Q.m[i][i] = 1.0;
    for (int m = 0; m < L_CH; m++) Q = mm4(Q, Abar);
    for (int rr = 0; rr < NROUND; rr++) {
        for (int i = 0; i < 4; i++)
            for (int j = 0; j < 4; j++) r.Pk[rr][i * 4 + j] = (float)Q.m[i][j];
        Q = mm4(Q, Q);
    }
    return r;
}

// host-side compile-time copy (for scalar extraction)
constexpr CB CC = build_consts();

// device-side copy in constant memory, statically initialized at compile time
__constant__ CB dC = build_consts();

// individual scalars for the serial replay (immediate folding; non-odr-used)
constexpr float AB00 = CC.Ab[0],  AB01 = CC.Ab[1],  AB02 = CC.Ab[2],  AB03 = CC.Ab[3];
constexpr float AB10 = CC.Ab[4],  AB11 = CC.Ab[5],  AB12 = CC.Ab[6],  AB13 = CC.Ab[7];
constexpr float AB20 = CC.Ab[8],  AB21 = CC.Ab[9],  AB22 = CC.Ab[10], AB23 = CC.Ab[11];
constexpr float AB30 = CC.Ab[12], AB31 = CC.Ab[13], AB32 = CC.Ab[14], AB33 = CC.Ab[15];
constexpr float BB0 = CC.Bb[0], BB1 = CC.Bb[1], BB2 = CC.Bb[2], BB3 = CC.Bb[3];

// ================================================================================

// Static scratch (no allocs). B <= 8 supported.
__device__ float4 g_start[8 * NCHUNK * D_DIM];  // start-states, [b][j][d]

// tree-form recurrence step (depth 4): x = Abar*x + Bbar*hv
#define RSTEP(hv)                                                               \
    {                                                                           \
        float y0 = fmaf(AB01, x1, fmaf(AB00, x0, BB0 * (hv)))                   \
                 + fmaf(AB02, x2, AB03 * x3);                                   \
        float y1 = fmaf(AB11, x1, fmaf(AB10, x0, BB1 * (hv)))                   \
                 + fmaf(AB12, x2, AB13 * x3);                                   \
        float y2 = fmaf(AB21, x1, fmaf(AB20, x0, BB2 * (hv)))                   \
                 + fmaf(AB22, x2, AB23 * x3);                                   \
        float y3 = fmaf(AB31, x1, fmaf(AB30, x0, BB3 * (hv)))                   \
                 + fmaf(AB32, x2, AB33 * x3);                                   \
        x0 = y0; x1 = y1; x2 = y2; x3 = y3;                                     \
    }

// v = M*p + v  (M in __constant__ -> LDC, uniform across warp)
__device__ __forceinline__ float4 mvacc(const float (&M)[16], float4 p, float4 v) {
    float4 r;
    r.x = fmaf(M[0],  p.x, fmaf(M[1],  p.y, fmaf(M[2],  p.z, fmaf(M[3],  p.w, v.x))));
    r.y = fmaf(M[4],  p.x, fmaf(M[5],  p.y, fmaf(M[6],  p.z, fmaf(M[7],  p.w, v.y))));
    r.z = fmaf(M[8],  p.x, fmaf(M[9],  p.y, fmaf(M[10], p.z, fmaf(M[11], p.w, v.z))));
    r.w = fmaf(M[12], p.x, fmaf(M[13], p.y, fmaf(M[14], p.z, fmaf(M[15], p.w, v.w))));
    return r;
}

__device__ __forceinline__ float4 wfma(const float (&w)[4], float s, float4 v) {
    v.x = fmaf(w[0], s, v.x);
    v.y = fmaf(w[1], s, v.y);
    v.z = fmaf(w[2], s, v.z);
    v.w = fmaf(w[3], s, v.w);
    return v;
}

#define SSTR 5   // slab row stride in floats

// ---- Kernel A: per (b, 4-d group): parallel chunk end-states + in-block scan ----
__global__ __launch_bounds__(ATHR)
void hippo_scan(const float* __restrict__ h) {
    __shared__ float  sh[T_LEN * SSTR];
    __shared__ float4 s[2][ATHR];

    const int tid = threadIdx.x;
    const int g   = blockIdx.x;           // d-group (0..63)
    const int b   = blockIdx.y;
    const int d0  = g * DG;

    // stage slab: thread loads rows 2*tid, 2*tid+1 (one float4 each)
    {
        const float* hb = h + (size_t)b * T_LEN * D_DIM + d0;
        const int r0 = tid * 2;
        float4 a0 = __ldg((const float4*)(hb + (size_t)r0 * D_DIM));
        float4 a1 = __ldg((const float4*)(hb + (size_t)(r0 + 1) * D_DIM));
        float* p0 = sh + r0 * SSTR;
        p0[0] = a0.x; p0[1] = a0.y; p0[2] = a0.z; p0[3] = a0.w;
        float* p1 = sh + (r0 + 1) * SSTR;
        p1[0] = a1.x; p1[1] = a1.y; p1[2] = a1.z; p1[3] = a1.w;
    }
    __syncthreads();

    const int j  = tid >> 2;
    const int dd = tid & 3;
    const float* col = sh + (size_t)(j * L_CH) * SSTR + dd;

    // chunk end-state, parallel form: e = sum_s Wc[7-s] * h_s
    float hr[L_CH];
    #pragma unroll
    for (int t = 0; t < L_CH; t++) hr[t] = col[t * SSTR];

    float4 e0 = make_float4(0.f, 0.f, 0.f, 0.f);
    float4 e1 = make_float4(0.f, 0.f, 0.f, 0.f);
    #pragma unroll
    for (int t = 0; t < L_CH; t += 2) {
        e0 = wfma(dC.Wc[L_CH - 1 - t], hr[t], e0);
        e1 = wfma(dC.Wc[L_CH - 2 - t], hr[t + 1], e1);
    }
    float4 v = make_float4(e0.x + e1.x, e0.y + e1.y, e0.z + e1.z, e0.w + e1.w);

    int cur = 0;
    s[cur][tid] = v;
    __syncthreads();

    // Kogge-Stone affine scan, ping-pong buffers (1 sync/round)
    #pragma unroll
    for (int r = 0; r < NROUND; r++) {
        const int off = 1 << r;
        if (j >= off) {
            float4 prev = s[cur][tid - off * DG];
            v = mvacc(dC.Pk[r], prev, v);
        }
        s[cur ^ 1][tid] = v;
        cur ^= 1;
        __syncthreads();
    }

    float4 st = make_float4(0.f, 0.f, 0.f, 0.f);
    if (j > 0) st = s[cur][tid - DG];
    g_start[((size_t)b * NCHUNK + j) * D_DIM + d0 + dd] = st;
}

// ---- Kernel B: single-wave serial replay. block = chunk j, 512 thr = 2 batches x 256 d ----
__global__ __launch_bounds__(512)
void hippo_k2(const float* __restrict__ h, float* __restrict__ out, int B) {
    __shared__ float sh[2 * L_CH * D_DIM];   // 16KB: two chunk slabs

    const int tid = threadIdx.x;
    const int j   = blockIdx.x;
    const int b0  = blockIdx.y * 2;
    const int bs  = tid >> 8;                // 0/1: batch half
    const int d   = tid & (D_DIM - 1);
    const int b   = b0 + bs;
    const bool act = (b < B);

    // stage both batch slabs: 1024 float4 total, 2 per thread (coalesced)
    {
        const float4* src0 = (const float4*)(h + ((size_t)(b0 * T_LEN + j * L_CH)) * D_DIM);
        ((float4*)sh)[tid] = __ldg(src0 + tid);
        if (b0 + 1 < B) {
            const float4* src1 = (const float4*)(h + ((size_t)((b0 + 1) * T_LEN + j * L_CH)) * D_DIM);
            ((float4*)sh)[512 + tid] = __ldg(src1 + tid);
        }
    }

    // start state (independent load, overlaps staging)
    float4 xs = make_float4(0.f, 0.f, 0.f, 0.f);
    if (act) xs = g_start[((size_t)b * NCHUNK + j) * D_DIM + d];
    __syncthreads();

    float x0 = xs.x, x1 = xs.y, x2 = xs.z, x3 = xs.w;
    const float* hp = sh + bs * (L_CH * D_DIM) + d;
    float* op = out + ((size_t)(b * T_LEN + j * L_CH)) * K_CH * D_DIM + d;

    #pragma unroll
    for (int t = 0; t < L_CH; t++) {
        float hv = hp[t * D_DIM];
        RSTEP(hv);
        if (act) {
            op[0]         = x0;
            op[D_DIM]     = x1;
            op[2 * D_DIM] = x2;
            op[3 * D_DIM] = x3;
        }
        op += (size_t)K_CH * D_DIM;
    }
}

extern "C" void kernel_launch(void* const* d_in, const int* in_sizes, int n_in,
                              void* d_out, int out_size) {
    const float* h;
    int sz0 = in_sizes[0], sz1 = in_sizes[1];
    if (sz0 > sz1) h = (const float*)d_in[0];
    else           h = (const float*)d_in[1];
    int hsz = (sz0 > sz1) ? sz0 : sz1;
    int B = hsz / (T_LEN * D_DIM);

    dim3 gridA(D_DIM / DG, B);               // 64 x B = 128 blocks (one wave)
    dim3 gridB(NCHUNK, (B + 1) / 2);         // 128 x ceil(B/2) blocks (one wave)
    hippo_scan<<<gridA, ATHR>>>(h);
    hippo_k2<<<gridB, 512>>>(h, (float*)d_out, B);
}

// round 12
// speedup vs baseline: 1.0209x; 1.0209x over previous
#include <cuda_runtime.h>

#define T_LEN  1024
#define D_DIM  256
#define K_CH   4
#define NCHUNK 128
#define L_CH   8          // T_LEN / NCHUNK
#define NROUND 7          // log2(NCHUNK)
#define DG     4          // d-columns per scan block
#define ATHR   (NCHUNK * DG)   // 512 threads in kernel A

// ================= compile-time HiPPO-LegT constants (double precision) ==========

struct CB {
    float Ab[16];
    float Bb[4];
    float Wc[L_CH][4];         // Abar^m * Bbar
    float Pk[NROUND][16];      // Abar^(L_CH * 2^r)
};

constexpr double cfabs(double x) { return x < 0 ? -x : x; }
constexpr double csqrt(double x) {
    double g = x > 1.0 ? x : 1.0;
    for (int i = 0; i < 128; i++) g = 0.5 * (g + x / g);
    return g;
}

struct M4d { double m[4][4]; };

constexpr M4d mm4(const M4d& A, const M4d& B) {
    M4d C{};
    for (int i = 0; i < 4; i++)
        for (int j = 0; j < 4; j++) {
            double s = 0.0;
            for (int k = 0; k < 4; k++) s += A.m[i][k] * B.m[k][j];
            C.m[i][j] = s;
        }
    return C;
}

constexpr M4d inv4(const M4d& Min) {
    double a[4][8] = {};
    for (int i = 0; i < 4; i++)
        for (int j = 0; j < 8; j++)
            a[i][j] = (j < 4) ? Min.m[i][j] : (j - 4 == i ? 1.0 : 0.0);
    for (int col = 0; col < 4; col++) {
        int p = col;
        for (int r = col + 1; r < 4; r++)
            if (cfabs(a[r][col]) > cfabs(a[p][col])) p = r;
        if (p != col)
            for (int j = 0; j < 8; j++) { double t = a[col][j]; a[col][j] = a[p][j]; a[p][j] = t; }
        double piv = a[col][col];
        for (int j = 0; j < 8; j++) a[col][j] /= piv;
        for (int r = 0; r < 4; r++) {
            if (r == col) continue;
            double f = a[r][col];
            for (int j = 0; j < 8; j++) a[r][j] -= f * a[col][j];
        }
    }
    M4d out{};
    for (int i = 0; i < 4; i++)
        for (int j = 0; j < 4; j++) out.m[i][j] = a[i][j + 4];
    return out;
}

constexpr CB build_consts() {
    const double dt = 1.0 / 200.0;
    double P[4] = {};
    for (int i = 0; i < 4; i++) P[i] = csqrt(2.0 * i + 1.0);
    M4d A{};
    double Bv[4] = {};
    for (int i = 0; i < 4; i++) {
        Bv[i] = P[i];
        for (int j = 0; j < 4; j++) {
            double sg = 1.0;
            if (j > i && ((j - i) & 1)) sg = -1.0;
            A.m[i][j] = -P[i] * P[j] * sg;
        }
    }
    M4d ImA{}, IpA{};
    for (int i = 0; i < 4; i++)
        for (int j = 0; j < 4; j++) {
            double eye = (i == j) ? 1.0 : 0.0;
            ImA.m[i][j] = eye - 0.5 * dt * A.m[i][j];
            IpA.m[i][j] = eye + 0.5 * dt * A.m[i][j];
        }
    M4d Inv = inv4(ImA);
    M4d Abar = mm4(Inv, IpA);
    double Bbar[4] = {};
    for (int i = 0; i < 4; i++) {
        double s = 0.0;
        for (int j = 0; j < 4; j++) s += Inv.m[i][j] * Bv[j] * dt;
        Bbar[i] = s;
    }

    CB r{};
    for (int i = 0; i < 4; i++) {
        r.Bb[i] = (float)Bbar[i];
        for (int j = 0; j < 4; j++) r.Ab[i * 4 + j] = (float)Abar.m[i][j];
    }
    double wc[4] = {Bbar[0], Bbar[1], Bbar[2], Bbar[3]};
    for (int m = 0; m < L_CH; m++) {
        for (int i = 0; i < 4; i++) r.Wc[m][i] = (float)wc[i];
        double nw[4] = {};
        for (int i = 0; i < 4; i++) {
            double s = 0.0;
            for (int j = 0; j < 4; j++) s += Abar.m[i][j] * wc[j];
            nw[i] = s;
        }
        for (int i = 0; i < 4; i++) wc[i] = nw[i];
    }
    M4d Q{};
    for (int i = 0; i < 4; i++) Q.m[i][i] = 1.0;
    for (int m = 0; m < L_CH; m++) Q = mm4(Q, Abar);
    for (int rr = 0; rr < NROUND; rr++) {
        for (int i = 0; i < 4; i++)
            for (int j = 0; j < 4; j++) r.Pk[rr][i * 4 + j] = (float)Q.m[i][j];
        Q = mm4(Q, Q);
    }
    return r;
}

constexpr CB CC = build_consts();
__constant__ CB dC = build_consts();

constexpr float AB00 = CC.Ab[0],  AB01 = CC.Ab[1],  AB02 = CC.Ab[2],  AB03 = CC.Ab[3];
constexpr float AB10 = CC.Ab[4],  AB11 = CC.Ab[5],  AB12 = CC.Ab[6],  AB13 = CC.Ab[7];
constexpr float AB20 = CC.Ab[8],  AB21 = CC.Ab[9],  AB22 = CC.Ab[10], AB23 = CC.Ab[11];
constexpr float AB30 = CC.Ab[12], AB31 = CC.Ab[13], AB32 = CC.Ab[14], AB33 = CC.Ab[15];
constexpr float BB0 = CC.Bb[0], BB1 = CC.Bb[1], BB2 = CC.Bb[2], BB3 = CC.Bb[3];

// ================================================================================

__device__ float4 g_start[8 * NCHUNK * D_DIM];  // start-states, [b][j][d]; B <= 8

#define RSTEP(hv)                                                               \
    {                                                                           \
        float y0 = fmaf(AB01, x1, fmaf(AB00, x0, BB0 * (hv)))                   \
                 + fmaf(AB02, x2, AB03 * x3);                                   \
        float y1 = fmaf(AB11, x1, fmaf(AB10, x0, BB1 * (hv)))                   \
                 + fmaf(AB12, x2, AB13 * x3);                                   \
        float y2 = fmaf(AB21, x1, fmaf(AB20, x0, BB2 * (hv)))                   \
                 + fmaf(AB22, x2, AB23 * x3);                                   \
        float y3 = fmaf(AB31, x1, fmaf(AB30, x0, BB3 * (hv)))                   \
                 + fmaf(AB32, x2, AB33 * x3);                                   \
        x0 = y0; x1 = y1; x2 = y2; x3 = y3;                                     \
    }

__device__ __forceinline__ float4 mvacc(const float (&M)[16], float4 p, float4 v) {
    float4 r;
    r.x = fmaf(M[0],  p.x, fmaf(M[1],  p.y, fmaf(M[2],  p.z, fmaf(M[3],  p.w, v.x))));
    r.y = fmaf(M[4],  p.x, fmaf(M[5],  p.y, fmaf(M[6],  p.z, fmaf(M[7],  p.w, v.y))));
    r.z = fmaf(M[8],  p.x, fmaf(M[9],  p.y, fmaf(M[10], p.z, fmaf(M[11], p.w, v.z))));
    r.w = fmaf(M[12], p.x, fmaf(M[13], p.y, fmaf(M[14], p.z, fmaf(M[15], p.w, v.w))));
    return r;
}

__device__ __forceinline__ float4 wfma(const float (&w)[4], float s, float4 v) {
    v.x = fmaf(w[0], s, v.x);
    v.y = fmaf(w[1], s, v.y);
    v.z = fmaf(w[2], s, v.z);
    v.w = fmaf(w[3], s, v.w);
    return v;
}

#define SSTR 5

// ---- Kernel A: chunk end-states + in-block Kogge-Stone scan; PDL trigger at end ----
__global__ __launch_bounds__(ATHR)
void hippo_scan(const float* __restrict__ h) {
    __shared__ float  sh[T_LEN * SSTR];
    __shared__ float4 s[2][ATHR];

    const int tid = threadIdx.x;
    const int g   = blockIdx.x;
    const int b   = blockIdx.y;
    const int d0  = g * DG;

    {
        const float* hb = h + (size_t)b * T_LEN * D_DIM + d0;
        const int r0 = tid * 2;
        float4 a0 = __ldg((const float4*)(hb + (size_t)r0 * D_DIM));
        float4 a1 = __ldg((const float4*)(hb + (size_t)(r0 + 1) * D_DIM));
        float* p0 = sh + r0 * SSTR;
        p0[0] = a0.x; p0[1] = a0.y; p0[2] = a0.z; p0[3] = a0.w;
        float* p1 = sh + (r0 + 1) * SSTR;
        p1[0] = a1.x; p1[1] = a1.y; p1[2] = a1.z; p1[3] = a1.w;
    }
    __syncthreads();

    const int j  = tid >> 2;
    const int dd = tid & 3;
    const float* col = sh + (size_t)(j * L_CH) * SSTR + dd;

    float hr[L_CH];
    #pragma unroll
    for (int t = 0; t < L_CH; t++) hr[t] = col[t * SSTR];

    float4 e0 = make_float4(0.f, 0.f, 0.f, 0.f);
    float4 e1 = make_float4(0.f, 0.f, 0.f, 0.f);
    #pragma unroll
    for (int t = 0; t < L_CH; t += 2) {
        e0 = wfma(dC.Wc[L_CH - 1 - t], hr[t], e0);
        e1 = wfma(dC.Wc[L_CH - 2 - t], hr[t + 1], e1);
    }
    float4 v = make_float4(e0.x + e1.x, e0.y + e1.y, e0.z + e1.z, e0.w + e1.w);

    int cur = 0;
    s[cur][tid] = v;
    __syncthreads();

    #pragma unroll
    for (int r = 0; r < NROUND; r++) {
        const int off = 1 << r;
        if (j >= off) {
            float4 prev = s[cur][tid - off * DG];
            v = mvacc(dC.Pk[r], prev, v);
        }
        s[cur ^ 1][tid] = v;
        cur ^= 1;
        __syncthreads();
    }

    float4 st = make_float4(0.f, 0.f, 0.f, 0.f);
    if (j > 0) st = s[cur][tid - DG];
    g_start[((size_t)b * NCHUNK + j) * D_DIM + d0 + dd] = st;

    // PDL: writes above are guaranteed visible to dependents after their wait
    asm volatile("griddepcontrol.launch_dependents;" ::: "memory");
}

// ---- Kernel B: no smem; h loads issue BEFORE the PDL wait, g_start after ----
__global__ __launch_bounds__(D_DIM)
void hippo_k2(const float* __restrict__ h, float* __restrict__ out) {
    const int d = threadIdx.x;
    const int j = blockIdx.x;
    const int b = blockIdx.y;

    // prelude (independent of kernel A): 8 coalesced, L2-hot loads into registers
    const float* hp = h + ((size_t)(b * T_LEN + j * L_CH)) * D_DIM + d;
    float hv[L_CH];
    #pragma unroll
    for (int t = 0; t < L_CH; t++) hv[t] = __ldg(hp + (size_t)t * D_DIM);

    // wait for kernel A's g_start writes
    asm volatile("griddepcontrol.wait;" ::: "memory");

    float4 xs = g_start[((size_t)b * NCHUNK + j) * D_DIM + d];
    float x0 = xs.x, x1 = xs.y, x2 = xs.z, x3 = xs.w;

    float* op = out + ((size_t)(b * T_LEN + j * L_CH)) * K_CH * D_DIM + d;
    #pragma unroll
    for (int t = 0; t < L_CH; t++) {
        RSTEP(hv[t]);
        op[0]         = x0;
        op[D_DIM]     = x1;
        op[2 * D_DIM] = x2;
        op[3 * D_DIM] = x3;
        op += (size_t)K_CH * D_DIM;
    }
}

extern "C" void kernel_launch(void* const* d_in, const int* in_sizes, int n_in,
                              void* d_out, int out_size) {
    const float* h;
    int sz0 = in_sizes[0], sz1 = in_sizes[1];
    if (sz0 > sz1) h = (const float*)d_in[0];
    else           h = (const float*)d_in[1];
    int hsz = (sz0 > sz1) ? sz0 : sz1;
    int B = hsz / (T_LEN * D_DIM);

    // Kernel A: normal launch
    dim3 gridA(D_DIM / DG, B);
    hippo_scan<<<gridA, ATHR>>>(h);

    // Kernel B: programmatic dependent launch (overlaps its prelude with A's tail)
    cudaLaunchConfig_t cfg = {};
    cfg.gridDim  = dim3(NCHUNK, B);
    cfg.blockDim = dim3(D_DIM);
    cfg.dynamicSmemBytes = 0;
    cfg.stream = 0;
    cudaLaunchAttribute attrs[1];
    attrs[0].id = cudaLaunchAttributeProgrammaticStreamSerialization;
    attrs[0].val.programmaticStreamSerializationAllowed = 1;
    cfg.attrs = attrs;
    cfg.numAttrs = 1;
    cudaLaunchKernelEx(&cfg, hippo_k2, h, (float*)d_out);
}